// round 12
// baseline (speedup 1.0000x reference)
#include <cuda_runtime.h>
#include <cstdint>

#define CIN   128
#define CHID  256
#define COUT  128
#define HW    1600
#define TP    64
#define NT    256
#define NTILE 25

#define SX 72      // x row stride (mod 32 == 8 -> conflict-free paired LDS.64)
#define SH 40      // h row stride (mod 32 == 8)

// SMEM float offsets
#define OXS 0                        // x [128 c][72], columns pair-permuted
#define OHB 9216                     // h: 2 halves x 2 bufs x [64 ch][40]
#define HSZ 2560
#define OGB 19456                    // gated b2 [128]
#define SMB ((19456 + 128) * 4)      // 78336 B -> 2 CTAs/SM

// weights packed in per-warp fragment order, tf32-rounded (1MB each)
__device__ float2 sW1p[131072];
__device__ float2 sW2p[131072];
__device__ int    g_idx[256];

__device__ __forceinline__ float tf32f(float v) {
    uint32_t r;
    asm("cvt.rna.tf32.f32 %0, %1;" : "=r"(r) : "f"(v));
    return __uint_as_float(r);
}
__device__ __forceinline__ void mma8(float (&d)[4], const float (&a)[4], float b0, float b1) {
    asm("mma.sync.aligned.m16n8k8.row.col.f32.tf32.tf32.f32 "
        "{%0,%1,%2,%3}, {%4,%5,%6,%7}, {%8,%9}, {%0,%1,%2,%3};"
        : "+f"(d[0]), "+f"(d[1]), "+f"(d[2]), "+f"(d[3])
        : "r"(__float_as_uint(a[0])), "r"(__float_as_uint(a[1])),
          "r"(__float_as_uint(a[2])), "r"(__float_as_uint(a[3])),
          "r"(__float_as_uint(b0)),  "r"(__float_as_uint(b1)));
}
#define HBAR(id) asm volatile("bar.sync %0, 128;" :: "r"(id) : "memory")

__global__ void prep_idx(const int* __restrict__ raw) {
    __shared__ int odd_nz;
    if (threadIdx.x == 0) odd_nz = 0;
    __syncthreads();
    if (threadIdx.x < 128) {
        if (raw[2 * threadIdx.x + 1] != 0) atomicAdd(&odd_nz, 1);
    }
    __syncthreads();
    bool is64 = (odd_nz == 0);
    g_idx[threadIdx.x] = is64 ? raw[2 * threadIdx.x] : raw[threadIdx.x];
}

// Pack weights into per-warp fragment order (layout identical to R8-R11).
__global__ void prep_w(const float* __restrict__ W1, const float* __restrict__ W2) {
    int tid = blockIdx.x * blockDim.x + threadIdx.x;   // 0..131071
    int lane = tid & 31, g = lane >> 2, t = lane & 3;
    {
        int half = (tid >> 5) & 1, k = (tid >> 6) & 15, wm = (tid >> 10) & 3;
        int j = (tid >> 12) & 3,  e = (tid >> 14) & 7;
        int ch = j * 64 + wm * 16 + half * 8 + g;
        int c  = 8 * k + t;
        const float* s = W1 + (size_t)e * 32768 + (size_t)ch * 128;
        sW1p[tid] = make_float2(tf32f(s[c]), tf32f(s[c + 4]));
    }
    {
        int half = (tid >> 5) & 1, k = (tid >> 6) & 7, mb = (tid >> 9) & 7;
        int j = (tid >> 12) & 3,  e = (tid >> 14) & 7;
        int oc = mb * 16 + half * 8 + g;
        int ch = j * 64 + 8 * k + t;
        const float* s = W2 + (size_t)e * 32768 + (size_t)oc * 256;
        sW2p[tid] = make_float2(tf32f(s[ch]), tf32f(s[ch + 4]));
    }
}

__global__ __launch_bounds__(NT, 2)
void moe_tf32(const float* __restrict__ x,
              const float* __restrict__ gate_w,
              const float* __restrict__ b1,
              const float* __restrict__ b2,
              float* __restrict__ out)
{
    extern __shared__ float sm[];
    const int tid  = threadIdx.x;
    const int lane = tid & 31;
    const int warp = tid >> 5;
    const int g    = lane >> 2;
    const int t    = lane & 3;
    const int hf   = warp >> 2;        // half: 0 -> px [0,32), 1 -> px [32,64)
    const int wm   = warp & 3;         // ch/oc block within half
    const int PX0  = hf * 32;
    const int b    = blockIdx.y;
    const int p0   = blockIdx.x * TP;

    const int   e0 = g_idx[b * 2],           e1 = g_idx[b * 2 + 1];
    const float g0 = __ldg(&gate_w[b * 2]);
    const float g1 = __ldg(&gate_w[b * 2 + 1]);

    if (tid < 128)
        sm[OGB + tid] = g0 * __ldg(&b2[e0 * COUT + tid]) + g1 * __ldg(&b2[e1 * COUT + tid]);

    // fragment prefetch rings
    float2 g1r[3][2];    // GEMM1: depth-3
    float2 g2r[2][4];    // GEMM2: depth-2

    // ---- prologue preload: GEMM1(it=0) fragments k=0..2 ----
    {
        const float2* pk1 = sW1p + (size_t)((e0 * 4 + 0) * 4 + wm) * 1024 + lane;
        g1r[0][0] = __ldg(pk1);       g1r[0][1] = __ldg(pk1 + 32);
        g1r[1][0] = __ldg(pk1 + 64);  g1r[1][1] = __ldg(pk1 + 96);
        g1r[2][0] = __ldg(pk1 + 128); g1r[2][1] = __ldg(pk1 + 160);
    }

    // ---- stage x pair-permuted + tf32-rounded ----
    {
        const float* xb = x + (size_t)b * CIN * HW + p0;
        #pragma unroll
        for (int i = 0; i < 4; i++) {
            int u = tid + i * NT;
            int c = u >> 3, blk = (u >> 1) & 3, h4 = u & 1;
            const float* src = xb + (size_t)c * HW + blk * 16 + h4 * 4;
            float4 lo = *(const float4*)(src);
            float4 hi = *(const float4*)(src + 8);
            float* dst = sm + OXS + c * SX + blk * 16 + h4 * 8;
            *(float2*)(dst + 0) = make_float2(tf32f(lo.x), tf32f(hi.x));
            *(float2*)(dst + 2) = make_float2(tf32f(lo.y), tf32f(hi.y));
            *(float2*)(dst + 4) = make_float2(tf32f(lo.z), tf32f(hi.z));
            *(float2*)(dst + 6) = make_float2(tf32f(lo.w), tf32f(hi.w));
        }
    }
    __syncthreads();   // x + gated-b2 visible

    float* const hbuf0 = sm + OHB + hf * 2 * HSZ;
    float* const hbuf1 = hbuf0 + HSZ;

    float acc2[2][4][4];
    #pragma unroll
    for (int m = 0; m < 2; m++)
        #pragma unroll
        for (int n = 0; n < 4; n++)
            #pragma unroll
            for (int q = 0; q < 4; q++) acc2[m][n][q] = 0.f;

    #pragma unroll 1
    for (int it = 0; it < 8; it++) {
        const int   e    = (it < 4) ? e0 : e1;
        const int   j    = it & 3;
        const float gate = (it < 4) ? g0 : g1;

        // ---- GEMM1(it): depth-3 pipelined fragment ring ----
        float acc1[4][4];
        #pragma unroll
        for (int n = 0; n < 4; n++)
            #pragma unroll
            for (int q = 0; q < 4; q++) acc1[n][q] = 0.f;
        {
            const float2* pk1 = sW1p + (size_t)((e * 4 + j) * 4 + wm) * 1024 + lane;
            #pragma unroll
            for (int k = 0; k < 16; k++) {
                const int s = k % 3;
                float a[4] = {g1r[s][0].x, g1r[s][1].x, g1r[s][0].y, g1r[s][1].y};
                if (k < 13) {
                    const int sn = (k + 3) % 3;
                    g1r[sn][0] = __ldg(pk1 + (k + 3) * 64);
                    g1r[sn][1] = __ldg(pk1 + (k + 3) * 64 + 32);
                }
                const float* xr0 = sm + OXS + (8 * k + t) * SX + PX0;
                const float* xr1 = xr0 + 4 * SX;
                float2 p00 = *(const float2*)(xr0 + 2 * g);
                float2 p10 = *(const float2*)(xr1 + 2 * g);
                float2 p01 = *(const float2*)(xr0 + 16 + 2 * g);
                float2 p11 = *(const float2*)(xr1 + 16 + 2 * g);
                mma8(acc1[0], a, p00.x, p10.x);
                mma8(acc1[1], a, p00.y, p10.y);
                mma8(acc1[2], a, p01.x, p11.x);
                mma8(acc1[3], a, p01.y, p11.y);
            }
        }

        // ---- GEMM2(it-1): depth-2 pipelined ring (preloaded last epilogue) ----
        if (it > 0) {
            const int ep = (it - 1 < 4) ? e0 : e1;
            const int jp = (it - 1) & 3;
            const float* hb = ((it - 1) & 1) ? hbuf1 : hbuf0;
            const float2* pk2 = sW2p + (size_t)((ep * 4 + jp) * 4096) + (wm * 2) * 512 + lane;
            #pragma unroll
            for (int k = 0; k < 8; k++) {
                const int s = k & 1;
                float a0[4] = {g2r[s][0].x, g2r[s][1].x, g2r[s][0].y, g2r[s][1].y};
                float a1[4] = {g2r[s][2].x, g2r[s][3].x, g2r[s][2].y, g2r[s][3].y};
                if (k < 6) {
                    g2r[s][0] = __ldg(pk2 + (k + 2) * 64);
                    g2r[s][1] = __ldg(pk2 + (k + 2) * 64 + 32);
                    g2r[s][2] = __ldg(pk2 + 512 + (k + 2) * 64);
                    g2r[s][3] = __ldg(pk2 + 512 + (k + 2) * 64 + 32);
                }
                const float* hr0 = hb + (8 * k + t) * SH;
                const float* hr1 = hr0 + 4 * SH;
                float2 q00 = *(const float2*)(hr0 + 2 * g);
                float2 q10 = *(const float2*)(hr1 + 2 * g);
                float2 q01 = *(const float2*)(hr0 + 16 + 2 * g);
                float2 q11 = *(const float2*)(hr1 + 16 + 2 * g);
                mma8(acc2[0][0], a0, q00.x, q10.x);
                mma8(acc2[1][0], a1, q00.x, q10.x);
                mma8(acc2[0][1], a0, q00.y, q10.y);
                mma8(acc2[1][1], a1, q00.y, q10.y);
                mma8(acc2[0][2], a0, q01.x, q11.x);
                mma8(acc2[1][2], a1, q01.x, q11.x);
                mma8(acc2[0][3], a0, q01.y, q11.y);
                mma8(acc2[1][3], a1, q01.y, q11.y);
            }
        }

        // ---- epilogue: bias + SiLU + gate -> h[it&1]; preload next fragments ----
        {
            const float bia0 = __ldg(b1 + e * CHID + j * 64 + wm * 16 + g);
            const float bia1 = __ldg(b1 + e * CHID + j * 64 + wm * 16 + 8 + g);
            float* hb = (it & 1) ? hbuf1 : hbuf0;
            int ch = wm * 16 + g;
            #pragma unroll
            for (int ni = 0; ni < 4; ni++) {
                int loc = (ni >> 1) * 16 + 4 * t + (ni & 1);
                float v0 = acc1[ni][0] + bia0;
                float v1 = acc1[ni][1] + bia0;
                float v2 = acc1[ni][2] + bia1;
                float v3 = acc1[ni][3] + bia1;
                float h0 = gate * (v0 / (1.f + __expf(-v0)));
                float h1 = gate * (v1 / (1.f + __expf(-v1)));
                float h2 = gate * (v2 / (1.f + __expf(-v2)));
                float h3 = gate * (v3 / (1.f + __expf(-v3)));
                hb[ch * SH + loc]           = tf32f(h0);
                hb[ch * SH + loc + 2]       = tf32f(h1);
                hb[(ch + 8) * SH + loc]     = tf32f(h2);
                hb[(ch + 8) * SH + loc + 2] = tf32f(h3);
            }

            // preload GEMM1(it+1) fragments k=0..2 (crosses the barrier)
            if (it < 7) {
                const int en = (it + 1 < 4) ? e0 : e1;
                const int jn = (it + 1) & 3;
                const float2* pk1n = sW1p + (size_t)((en * 4 + jn) * 4 + wm) * 1024 + lane;
                g1r[0][0] = __ldg(pk1n);       g1r[0][1] = __ldg(pk1n + 32);
                g1r[1][0] = __ldg(pk1n + 64);  g1r[1][1] = __ldg(pk1n + 96);
                g1r[2][0] = __ldg(pk1n + 128); g1r[2][1] = __ldg(pk1n + 160);
            }
            // preload GEMM2(it) fragments k=0,1 (consumed next iteration / tail)
            {
                const float2* pk2c = sW2p + (size_t)((e * 4 + j) * 4096) + (wm * 2) * 512 + lane;
                g2r[0][0] = __ldg(pk2c);       g2r[0][1] = __ldg(pk2c + 32);
                g2r[0][2] = __ldg(pk2c + 512); g2r[0][3] = __ldg(pk2c + 544);
                g2r[1][0] = __ldg(pk2c + 64);  g2r[1][1] = __ldg(pk2c + 96);
                g2r[1][2] = __ldg(pk2c + 576); g2r[1][3] = __ldg(pk2c + 608);
            }
        }
        HBAR(hf + 1);   // publish h(it) within this 4-warp half
    }

    // ---- tail: GEMM2(7), fragments preloaded in epilogue(7) ----
    {
        const float* hb = hbuf1;
        const float2* pk2 = sW2p + (size_t)((e1 * 4 + 3) * 4096) + (wm * 2) * 512 + lane;
        #pragma unroll
        for (int k = 0; k < 8; k++) {
            const int s = k & 1;
            float a0[4] = {g2r[s][0].x, g2r[s][1].x, g2r[s][0].y, g2r[s][1].y};
            float a1[4] = {g2r[s][2].x, g2r[s][3].x, g2r[s][2].y, g2r[s][3].y};
            if (k < 6) {
                g2r[s][0] = __ldg(pk2 + (k + 2) * 64);
                g2r[s][1] = __ldg(pk2 + (k + 2) * 64 + 32);
                g2r[s][2] = __ldg(pk2 + 512 + (k + 2) * 64);
                g2r[s][3] = __ldg(pk2 + 512 + (k + 2) * 64 + 32);
            }
            const float* hr0 = hb + (8 * k + t) * SH;
            const float* hr1 = hr0 + 4 * SH;
            float2 q00 = *(const float2*)(hr0 + 2 * g);
            float2 q10 = *(const float2*)(hr1 + 2 * g);
            float2 q01 = *(const float2*)(hr0 + 16 + 2 * g);
            float2 q11 = *(const float2*)(hr1 + 16 + 2 * g);
            mma8(acc2[0][0], a0, q00.x, q10.x);
            mma8(acc2[1][0], a1, q00.x, q10.x);
            mma8(acc2[0][1], a0, q00.y, q10.y);
            mma8(acc2[1][1], a1, q00.y, q10.y);
            mma8(acc2[0][2], a0, q01.x, q11.x);
            mma8(acc2[1][2], a1, q01.x, q11.x);
            mma8(acc2[0][3], a0, q01.y, q11.y);
            mma8(acc2[1][3], a1, q01.y, q11.y);
        }
    }

    // ---- final store: acc2 + gated b2 -> out ----
    {
        float* ob = out + (size_t)b * COUT * HW + p0 + PX0;
        #pragma unroll
        for (int mi = 0; mi < 2; mi++) {
            int oc = wm * 32 + 16 * mi + g;
            float gba = sm[OGB + oc], gbb = sm[OGB + oc + 8];
            #pragma unroll
            for (int ni = 0; ni < 4; ni++) {
                int px = 8 * ni + 2 * t;
                *(float2*)(ob + (size_t)oc * HW + px) =
                    make_float2(acc2[mi][ni][0] + gba, acc2[mi][ni][1] + gba);
                *(float2*)(ob + (size_t)(oc + 8) * HW + px) =
                    make_float2(acc2[mi][ni][2] + gbb, acc2[mi][ni][3] + gbb);
            }
        }
    }
}

extern "C" void kernel_launch(void* const* d_in, const int* in_sizes, int n_in,
                              void* d_out, int out_size) {
    const float* x   = (const float*)d_in[0];
    const float* wts = (const float*)d_in[1];
    const int*   idx = (const int*)d_in[2];
    const float* W1  = (const float*)d_in[3];
    const float* b1  = (const float*)d_in[4];
    const float* W2  = (const float*)d_in[5];
    const float* b2  = (const float*)d_in[6];
    float* out = (float*)d_out;
    (void)in_sizes; (void)n_in; (void)out_size;

    prep_idx<<<1, 256>>>(idx);
    prep_w<<<256, 512>>>(W1, W2);

    cudaFuncSetAttribute(moe_tf32, cudaFuncAttributeMaxDynamicSharedMemorySize, SMB);
    dim3 grid(NTILE, 128);
    moe_tf32<<<grid, NT, SMB>>>(x, wts, b1, b2, out);
}